// round 1
// baseline (speedup 1.0000x reference)
#include <cuda_runtime.h>
#include <math.h>

#define BB 16
#define C1 128
#define C2 128
#define HH 64
#define WW 64
#define KK 3
#define K2 9

// scratch: offsets(18ch) + sigmoided mask(9ch), and transposed conv weights
__device__ float g_offmask[BB * 27 * HH * WW];  // [b][ch][h][w]
__device__ float g_wkT[K2 * C1 * C2];           // [n][c][oc]

// ---------------------------------------------------------------------------
// weight transpose: w_conv[oc][c][n] -> wkT[n][c][oc]
// ---------------------------------------------------------------------------
__global__ void wt_kernel(const float* __restrict__ w_conv) {
    int i = blockIdx.x * 256 + threadIdx.x;
    if (i < C2 * C1 * K2) {
        int oc = i / (C1 * K2);
        int r = i % (C1 * K2);
        int c = r / K2, n = r % K2;
        g_wkT[(n * C1 + c) * C2 + oc] = w_conv[i];
    }
}

// ---------------------------------------------------------------------------
// offset/mask conv: 27 output channels, 3x3, pad 1, over C1=128 inputs.
// tile 16x16 pixels per block, 256 threads (1 pixel each), 16-ch chunks.
// ---------------------------------------------------------------------------
__global__ void __launch_bounds__(256) offmask_kernel(
    const float* __restrict__ x,
    const float* __restrict__ w_off, const float* __restrict__ b_off,
    const float* __restrict__ w_mask, const float* __restrict__ b_mask)
{
    const int b = blockIdx.z;
    const int h0 = blockIdx.y * 16, w0 = blockIdx.x * 16;
    const int tid = threadIdx.x;
    const int ly = tid / 16, lx = tid % 16;

    __shared__ float patch[16][18][18];   // [c][y][x]
    __shared__ float wsh[27][16][9];      // [ch][c][k]

    float acc[27];
#pragma unroll
    for (int i = 0; i < 27; i++) acc[i] = 0.f;

    for (int c0 = 0; c0 < C1; c0 += 16) {
        // load input patch (with zero halo)
        for (int i = tid; i < 16 * 18 * 18; i += 256) {
            int c = i / (18 * 18);
            int r = i % (18 * 18);
            int py = r / 18, px = r % 18;
            int gy = h0 - 1 + py, gx = w0 - 1 + px;
            float v = 0.f;
            if (gy >= 0 && gy < HH && gx >= 0 && gx < WW)
                v = x[((b * C1 + c0 + c) * HH + gy) * WW + gx];
            patch[c][py][px] = v;
        }
        // load weight chunk (offset weights then mask weights)
        for (int i = tid; i < 27 * 16 * 9; i += 256) {
            int ch = i / (16 * 9);
            int r = i % (16 * 9);
            int c = r / 9, k = r % 9;
            float v;
            if (ch < 18) v = w_off[((ch) * C1 + c0 + c) * 9 + k];
            else         v = w_mask[((ch - 18) * C1 + c0 + c) * 9 + k];
            wsh[ch][c][k] = v;
        }
        __syncthreads();

#pragma unroll 1
        for (int c = 0; c < 16; c++) {
            float p[9];
#pragma unroll
            for (int ky = 0; ky < 3; ky++)
#pragma unroll
                for (int kx = 0; kx < 3; kx++)
                    p[ky * 3 + kx] = patch[c][ly + ky][lx + kx];
#pragma unroll
            for (int ch = 0; ch < 27; ch++) {
                float s = acc[ch];
#pragma unroll
                for (int k = 0; k < 9; k++) s = fmaf(p[k], wsh[ch][c][k], s);
                acc[ch] = s;
            }
        }
        __syncthreads();
    }

    const int h = h0 + ly, w = w0 + lx;
#pragma unroll
    for (int ch = 0; ch < 27; ch++) {
        float v = acc[ch] + (ch < 18 ? b_off[ch] : b_mask[ch - 18]);
        if (ch >= 18) v = 1.f / (1.f + __expf(-v));  // sigmoid for mask
        g_offmask[((b * 27 + ch) * HH + h) * WW + w] = v;
    }
}

// ---------------------------------------------------------------------------
// deformable sampling + contraction.
// block: 32 pixels (one row segment) x 128 output channels, 256 threads.
// loops: tap n (9), channel chunk (32). gather samp tile into smem, load
// weight tile wkT[n][c][oc], 4x4 register-blocked fp32 GEMM.
// ---------------------------------------------------------------------------
__global__ void __launch_bounds__(256) dcn_kernel(
    const float* __restrict__ x, float* __restrict__ out)
{
    const int b = blockIdx.z;
    const int h = blockIdx.y;
    const int w0 = blockIdx.x * 32;
    const int tid = threadIdx.x;

    __shared__ float sampS[32][36];      // [c][pix], padded stride
    __shared__ float wsS[32][128];       // [c][oc]
    __shared__ int   miY0[9][32], miY1[9][32], miX0[9][32], miX1[9][32];
    __shared__ float mw[9][32][4];       // corner weights * mask (boundary-zeroed)

    // phase 0: per-(tap,pixel) bilinear metadata
    for (int i = tid; i < 9 * 32; i += 256) {
        int n = i / 32, pix = i % 32;
        int wpix = w0 + pix;
        const float offY = g_offmask[((b * 27 + 2 * n)     * HH + h) * WW + wpix];
        const float offX = g_offmask[((b * 27 + 2 * n + 1) * HH + h) * WW + wpix];
        const float m    = g_offmask[((b * 27 + 18 + n)    * HH + h) * WW + wpix];
        float py = offY + (float)(h - 1 + n / 3);
        float px = offX + (float)(wpix - 1 + n % 3);
        float fy = floorf(py), fx = floorf(px);
        int y0 = (int)fy, x0 = (int)fx;
        float wy1 = py - fy, wx1 = px - fx;
        float wy0 = 1.f - wy1, wx0 = 1.f - wx1;
        int y1 = y0 + 1, x1 = x0 + 1;
        bool vy0 = (y0 >= 0 && y0 < HH), vy1 = (y1 >= 0 && y1 < HH);
        bool vx0 = (x0 >= 0 && x0 < WW), vx1 = (x1 >= 0 && x1 < WW);
        mw[n][pix][0] = (vy0 && vx0) ? wy0 * wx0 * m : 0.f;
        mw[n][pix][1] = (vy0 && vx1) ? wy0 * wx1 * m : 0.f;
        mw[n][pix][2] = (vy1 && vx0) ? wy1 * wx0 * m : 0.f;
        mw[n][pix][3] = (vy1 && vx1) ? wy1 * wx1 * m : 0.f;
        miY0[n][pix] = min(max(y0, 0), HH - 1);
        miY1[n][pix] = min(max(y1, 0), HH - 1);
        miX0[n][pix] = min(max(x0, 0), WW - 1);
        miX1[n][pix] = min(max(x1, 0), WW - 1);
    }
    __syncthreads();

    float acc[4][4];   // [pix][oc]
#pragma unroll
    for (int i = 0; i < 4; i++)
#pragma unroll
        for (int j = 0; j < 4; j++) acc[i][j] = 0.f;

    const int tx = tid % 32;   // oc group (4 oc each)
    const int ty = tid / 32;   // pix group (4 pix each)
    const int gp = tid % 32;   // gather: pixel
    const int gc = tid / 32;   // gather: channel lane (0..7)

    for (int n = 0; n < 9; n++) {
        const int   y0  = miY0[n][gp], y1 = miY1[n][gp];
        const int   x0i = miX0[n][gp], x1i = miX1[n][gp];
        const float w00 = mw[n][gp][0], w01 = mw[n][gp][1];
        const float w10 = mw[n][gp][2], w11 = mw[n][gp][3];

        for (int c0 = 0; c0 < C1; c0 += 32) {
            __syncthreads();   // protect smem reuse across chunks
            // gather samp tile: [32 c][32 pix]
#pragma unroll
            for (int j = 0; j < 4; j++) {
                int c = c0 + gc + j * 8;
                const float* xb = x + ((size_t)(b * C1 + c) * HH) * WW;
                float v = w00 * __ldg(xb + y0 * WW + x0i)
                        + w01 * __ldg(xb + y0 * WW + x1i)
                        + w10 * __ldg(xb + y1 * WW + x0i)
                        + w11 * __ldg(xb + y1 * WW + x1i);
                sampS[gc + j * 8][gp] = v;
            }
            // weight tile: wkT[n][c0..c0+31][0..127]
            for (int i = tid; i < 32 * 128; i += 256) {
                int c = i / 128, oc = i % 128;
                wsS[c][oc] = g_wkT[(n * C1 + c0 + c) * C2 + oc];
            }
            __syncthreads();

#pragma unroll
            for (int cc = 0; cc < 32; cc++) {
                const float4 a  = *(const float4*)&sampS[cc][ty * 4];
                const float4 wv = *(const float4*)&wsS[cc][tx * 4];
                float av[4] = {a.x, a.y, a.z, a.w};
                float wvv[4] = {wv.x, wv.y, wv.z, wv.w};
#pragma unroll
                for (int i = 0; i < 4; i++)
#pragma unroll
                    for (int j = 0; j < 4; j++)
                        acc[i][j] = fmaf(av[i], wvv[j], acc[i][j]);
            }
        }
    }

    // write out[b][oc][h][w], 4 pixels contiguous per store
#pragma unroll
    for (int j = 0; j < 4; j++) {
        int oc = tx * 4 + j;
        float4 v = make_float4(acc[0][j], acc[1][j], acc[2][j], acc[3][j]);
        *(float4*)&out[(((size_t)b * C2 + oc) * HH + h) * WW + w0 + ty * 4] = v;
    }
}

// ---------------------------------------------------------------------------
extern "C" void kernel_launch(void* const* d_in, const int* in_sizes, int n_in,
                              void* d_out, int out_size) {
    const float* x      = (const float*)d_in[0];
    const float* w_conv = (const float*)d_in[1];
    const float* w_off  = (const float*)d_in[2];
    const float* b_off  = (const float*)d_in[3];
    const float* w_mask = (const float*)d_in[4];
    const float* b_mask = (const float*)d_in[5];
    float* out = (float*)d_out;

    // 1. transpose conv weights
    wt_kernel<<<(C2 * C1 * K2 + 255) / 256, 256>>>(w_conv);

    // 2. offset + mask conv
    dim3 gA(WW / 16, HH / 16, BB);
    offmask_kernel<<<gA, 256>>>(x, w_off, b_off, w_mask, b_mask);

    // 3. deformable sampling + contraction
    dim3 gB(WW / 32, HH, BB);
    dcn_kernel<<<gB, 256>>>(x, out);
}

// round 3
// speedup vs baseline: 1.6179x; 1.6179x over previous
#include <cuda_runtime.h>
#include <cuda_fp16.h>
#include <math.h>
#include <stdint.h>

#define BB 16
#define C1 128
#define C2 128
#define HH 64
#define WW 64
#define K2 9

// scratch
__device__ float  g_offmask[BB * 27 * HH * WW];     // [b][ch][h][w]
__device__ float  g_xT[(size_t)BB * HH * WW * C1];  // [b][h][w][c]
__device__ __half g_wk16[K2 * C2 * C1];             // [n][oc][c] fp16

// ---------------------------------------------------------------------------
__device__ __forceinline__ uint32_t smem_u32(const void* p) {
    uint32_t a;
    asm("{ .reg .u64 t; cvta.to.shared.u64 t, %1; cvt.u32.u64 %0, t; }" : "=r"(a) : "l"(p));
    return a;
}
__device__ __forceinline__ void ldsm4(uint32_t addr, uint32_t* r) {
    asm volatile("ldmatrix.sync.aligned.m8n8.x4.shared.b16 {%0,%1,%2,%3}, [%4];"
                 : "=r"(r[0]), "=r"(r[1]), "=r"(r[2]), "=r"(r[3]) : "r"(addr));
}
__device__ __forceinline__ void mma16816(float* c, const uint32_t* a, uint32_t b0, uint32_t b1) {
    asm volatile("mma.sync.aligned.m16n8k16.row.col.f32.f16.f16.f32 "
                 "{%0,%1,%2,%3}, {%4,%5,%6,%7}, {%8,%9}, {%0,%1,%2,%3};"
                 : "+f"(c[0]), "+f"(c[1]), "+f"(c[2]), "+f"(c[3])
                 : "r"(a[0]), "r"(a[1]), "r"(a[2]), "r"(a[3]), "r"(b0), "r"(b1));
}

// ---------------------------------------------------------------------------
// prep 1: transpose x[b][c][hw] -> g_xT[b][hw][c]
// ---------------------------------------------------------------------------
__global__ void __launch_bounds__(256) xT_kernel(const float* __restrict__ x) {
    __shared__ float t[128][33];
    const int b = blockIdx.y;
    const int pix0 = blockIdx.x * 32;
    const int px = threadIdx.x & 31, c0 = threadIdx.x >> 5;
#pragma unroll
    for (int k = 0; k < 16; k++) {
        int c = c0 + k * 8;
        t[c][px] = x[((size_t)(b * C1 + c) << 12) + pix0 + px];
    }
    __syncthreads();
    const int pix = threadIdx.x >> 3, cq = threadIdx.x & 7;
    float* dst = g_xT + (((size_t)b << 12) + pix0 + pix) * C1;
#pragma unroll
    for (int k = 0; k < 4; k++) {
        int ce = (cq + k * 8) * 4;
        float4 v = make_float4(t[ce][pix], t[ce + 1][pix], t[ce + 2][pix], t[ce + 3][pix]);
        ((float4*)dst)[ce >> 2] = v;
    }
}

// ---------------------------------------------------------------------------
// prep 2: w_conv[oc][c][n] -> g_wk16[n][oc][c] fp16
// ---------------------------------------------------------------------------
__global__ void wk16_kernel(const float* __restrict__ w_conv) {
    int i = blockIdx.x * 256 + threadIdx.x;
    if (i < K2 * C2 * C1) {
        int n = i / (C2 * C1);
        int r = i % (C2 * C1);
        int oc = r / C1, c = r % C1;
        g_wk16[i] = __float2half(w_conv[(oc * C1 + c) * K2 + n]);
    }
}

// ---------------------------------------------------------------------------
// offset/mask conv (fp32)
// ---------------------------------------------------------------------------
__global__ void __launch_bounds__(256) offmask_kernel(
    const float* __restrict__ x,
    const float* __restrict__ w_off, const float* __restrict__ b_off,
    const float* __restrict__ w_mask, const float* __restrict__ b_mask)
{
    const int b = blockIdx.z;
    const int h0 = blockIdx.y * 16, w0 = blockIdx.x * 16;
    const int tid = threadIdx.x;
    const int ly = tid / 16, lx = tid % 16;

    __shared__ float patch[16][18][18];
    __shared__ float wsh[27][16][9];

    float acc[27];
#pragma unroll
    for (int i = 0; i < 27; i++) acc[i] = 0.f;

    for (int c0 = 0; c0 < C1; c0 += 16) {
        for (int i = tid; i < 16 * 18 * 18; i += 256) {
            int c = i / (18 * 18);
            int r = i % (18 * 18);
            int py = r / 18, px = r % 18;
            int gy = h0 - 1 + py, gx = w0 - 1 + px;
            float v = 0.f;
            if (gy >= 0 && gy < HH && gx >= 0 && gx < WW)
                v = x[((b * C1 + c0 + c) * HH + gy) * WW + gx];
            patch[c][py][px] = v;
        }
        for (int i = tid; i < 27 * 16 * 9; i += 256) {
            int ch = i / (16 * 9);
            int r = i % (16 * 9);
            int c = r / 9, k = r % 9;
            float v;
            if (ch < 18) v = w_off[((ch) * C1 + c0 + c) * 9 + k];
            else         v = w_mask[((ch - 18) * C1 + c0 + c) * 9 + k];
            wsh[ch][c][k] = v;
        }
        __syncthreads();

#pragma unroll 1
        for (int c = 0; c < 16; c++) {
            float p[9];
#pragma unroll
            for (int ky = 0; ky < 3; ky++)
#pragma unroll
                for (int kx = 0; kx < 3; kx++)
                    p[ky * 3 + kx] = patch[c][ly + ky][lx + kx];
#pragma unroll
            for (int ch = 0; ch < 27; ch++) {
                float s = acc[ch];
#pragma unroll
                for (int k = 0; k < 9; k++) s = fmaf(p[k], wsh[ch][c][k], s);
                acc[ch] = s;
            }
        }
        __syncthreads();
    }

    const int h = h0 + ly, w = w0 + lx;
#pragma unroll
    for (int ch = 0; ch < 27; ch++) {
        float v = acc[ch] + (ch < 18 ? b_off[ch] : b_mask[ch - 18]);
        if (ch >= 18) v = 1.f / (1.f + __expf(-v));
        g_offmask[((b * 27 + ch) * HH + h) * WW + w] = v;
    }
}

// ---------------------------------------------------------------------------
// main DCN: 128 pixels x 128 oc per CTA, HMMA m16n8k16, fp32 register accum
// ---------------------------------------------------------------------------
#define SA 136                                  // A/B smem stride in halves
#define SMEM_A_OFF  0
#define SMEM_B_OFF  (128 * SA * 2)              // 34816
#define SMEM_MI_OFF (2 * 128 * SA * 2)          // 69632
#define SMEM_MW_OFF (SMEM_MI_OFF + 2048)
#define SMEM_TOTAL  (SMEM_MW_OFF + 2048)        // 73728

__global__ void __launch_bounds__(256, 2) dcn_kernel(float* __restrict__ out)
{
    extern __shared__ char smem[];
    const uint32_t sb = smem_u32(smem);
    __half* Bs = (__half*)(smem + SMEM_B_OFF);
    int4*   metaI = (int4*)(smem + SMEM_MI_OFF);
    float4* metaW = (float4*)(smem + SMEM_MW_OFF);

    const int tid = threadIdx.x;
    const int lane = tid & 31;
    const int warp = tid >> 5;
    const int warp_m = warp & 3;      // 4 row-groups of 32 pixels
    const int warp_n = warp >> 2;     // 2 col-groups of 64 oc
    const int b = blockIdx.x >> 5;
    const int h0 = (blockIdx.x & 31) << 1;

    float acc[2][8][4];
#pragma unroll
    for (int i = 0; i < 2; i++)
#pragma unroll
        for (int j = 0; j < 8; j++)
#pragma unroll
            for (int k = 0; k < 4; k++) acc[i][j][k] = 0.f;

    const int gpix_q = tid >> 3;      // 0..31 pixel within pass
    const int chq = tid & 7;          // 16-channel chunk

    for (int n = 0; n < 9; n++) {
        if (n) __syncthreads();       // prev tap's mma reads done before overwrite

        // ---- per-pixel bilinear metadata ----
        if (tid < 128) {
            const int pix = tid;
            const int h = h0 + (pix >> 6), w = pix & 63;
            const float* om = g_offmask + ((size_t)b * 27 << 12) + (h << 6) + w;
            float offY = om[(size_t)(2 * n) << 12];
            float offX = om[(size_t)(2 * n + 1) << 12];
            float m    = om[(size_t)(18 + n) << 12];
            float py = offY + (float)(h - 1 + n / 3);
            float px = offX + (float)(w - 1 + n % 3);
            float fy = floorf(py), fx = floorf(px);
            int y0 = (int)fy, x0 = (int)fx;
            float wy1 = py - fy, wx1 = px - fx;
            float wy0 = 1.f - wy1, wx0 = 1.f - wx1;
            int y1 = y0 + 1, x1 = x0 + 1;
            bool vy0 = (y0 >= 0) & (y0 < HH), vy1 = (y1 >= 0) & (y1 < HH);
            bool vx0 = (x0 >= 0) & (x0 < WW), vx1 = (x1 >= 0) & (x1 < WW);
            int y0c = min(max(y0, 0), HH - 1), y1c = min(max(y1, 0), HH - 1);
            int x0c = min(max(x0, 0), WW - 1), x1c = min(max(x1, 0), WW - 1);
            int base = (b << 12);
            metaI[pix] = make_int4((base + (y0c << 6) + x0c) << 7,
                                   (base + (y0c << 6) + x1c) << 7,
                                   (base + (y1c << 6) + x0c) << 7,
                                   (base + (y1c << 6) + x1c) << 7);
            metaW[pix] = make_float4((vy0 && vx0) ? wy0 * wx0 * m : 0.f,
                                     (vy0 && vx1) ? wy0 * wx1 * m : 0.f,
                                     (vy1 && vx0) ? wy1 * wx0 * m : 0.f,
                                     (vy1 && vx1) ? wy1 * wx1 * m : 0.f);
        }
        __syncthreads();

        // ---- gather + bilinear -> fp16 A tile [pix][c], stride SA ----
#pragma unroll
        for (int pass = 0; pass < 4; pass++) {
            const int pix = pass * 32 + gpix_q;
            const int4   mi = metaI[pix];
            const float4 mw = metaW[pix];
            const int ch0 = chq * 16;
            const float* p00 = g_xT + mi.x + ch0;
            const float* p01 = g_xT + mi.y + ch0;
            const float* p10 = g_xT + mi.z + ch0;
            const float* p11 = g_xT + mi.w + ch0;
            uint32_t rowbase = sb + SMEM_A_OFF + (uint32_t)(pix * SA + ch0) * 2;
#pragma unroll
            for (int j = 0; j < 4; j++) {
                float4 a  = ((const float4*)p00)[j];
                float4 bq = ((const float4*)p01)[j];
                float4 cq = ((const float4*)p10)[j];
                float4 dq = ((const float4*)p11)[j];
                float r0 = mw.x * a.x + mw.y * bq.x + mw.z * cq.x + mw.w * dq.x;
                float r1 = mw.x * a.y + mw.y * bq.y + mw.z * cq.y + mw.w * dq.y;
                float r2 = mw.x * a.z + mw.y * bq.z + mw.z * cq.z + mw.w * dq.z;
                float r3 = mw.x * a.w + mw.y * bq.w + mw.z * cq.w + mw.w * dq.w;
                __half2 hA = __floats2half2_rn(r0, r1);
                __half2 hB = __floats2half2_rn(r2, r3);
                uint32_t uA = *(uint32_t*)&hA;
                uint32_t uB = *(uint32_t*)&hB;
                asm volatile("st.shared.v2.b32 [%0], {%1, %2};"
                             :: "r"(rowbase + j * 8u), "r"(uA), "r"(uB) : "memory");
            }
        }

        // ---- B tile copy [oc][c] with padding ----
        {
            const float4* src = (const float4*)(g_wk16 + n * (C2 * C1));
            for (int i = tid; i < 2048; i += 256) {
                int row = i >> 4, seg = i & 15;
                *(float4*)(Bs + row * SA + seg * 8) = src[i];
            }
        }
        __syncthreads();

        // ---- HMMA over 8 k-steps ----
        const uint32_t rA = (uint32_t)(warp_m * 32 + (lane & 15));
        const uint32_t rB = (uint32_t)(warp_n * 64 + (lane & 15));
        const uint32_t cbase = (uint32_t)((lane >> 4) << 3);
#pragma unroll 2
        for (int kk = 0; kk < 8; kk++) {
            uint32_t col = kk * 16 + cbase;
            uint32_t a0[4], a1[4];
            ldsm4(sb + SMEM_A_OFF + (rA * SA + col) * 2, a0);
            ldsm4(sb + SMEM_A_OFF + ((rA + 16) * SA + col) * 2, a1);
            uint32_t bf[4][4];
#pragma unroll
            for (int t = 0; t < 4; t++)
                ldsm4(sb + SMEM_B_OFF + ((rB + t * 16) * SA + col) * 2, bf[t]);
#pragma unroll
            for (int t = 0; t < 4; t++) {
                mma16816(acc[0][2 * t],     a0, bf[t][0], bf[t][2]);
                mma16816(acc[0][2 * t + 1], a0, bf[t][1], bf[t][3]);
                mma16816(acc[1][2 * t],     a1, bf[t][0], bf[t][2]);
                mma16816(acc[1][2 * t + 1], a1, bf[t][1], bf[t][3]);
            }
        }
    }

    // ---- epilogue: acc -> out[b][oc][h][w] ----
    const size_t obase = ((size_t)b * C2 << 12) + (size_t)h0 * 64;
#pragma unroll
    for (int mt = 0; mt < 2; mt++) {
#pragma unroll
        for (int nt = 0; nt < 8; nt++) {
            const float* c = acc[mt][nt];
            int m0 = warp_m * 32 + mt * 16 + (lane >> 2);
            int n0 = warp_n * 64 + nt * 8 + (lane & 3) * 2;
            float* o0 = out + obase + ((size_t)n0 << 12);
            float* o1 = o0 + 4096;
            o0[m0]     = c[0];
            o1[m0]     = c[1];
            o0[m0 + 8] = c[2];
            o1[m0 + 8] = c[3];
        }
    }
}

// ---------------------------------------------------------------------------
extern "C" void kernel_launch(void* const* d_in, const int* in_sizes, int n_in,
                              void* d_out, int out_size) {
    const float* x      = (const float*)d_in[0];
    const float* w_conv = (const float*)d_in[1];
    const float* w_off  = (const float*)d_in[2];
    const float* b_off  = (const float*)d_in[3];
    const float* w_mask = (const float*)d_in[4];
    const float* b_mask = (const float*)d_in[5];
    float* out = (float*)d_out;

    cudaFuncSetAttribute(dcn_kernel, cudaFuncAttributeMaxDynamicSharedMemorySize, SMEM_TOTAL);

    wk16_kernel<<<(K2 * C2 * C1 + 255) / 256, 256>>>(w_conv);

    dim3 gT(HH * WW / 32, BB);
    xT_kernel<<<gT, 256>>>(x);

    dim3 gA(WW / 16, HH / 16, BB);
    offmask_kernel<<<gA, 256>>>(x, w_off, b_off, w_mask, b_mask);

    dcn_kernel<<<BB * HH / 2, 256, SMEM_TOTAL>>>(out);
}

// round 4
// speedup vs baseline: 5.9122x; 3.6542x over previous
#include <cuda_runtime.h>
#include <cuda_fp16.h>
#include <math.h>
#include <stdint.h>

#define BB 16
#define C1 128
#define C2 128
#define HH 64
#define WW 64
#define K2 9

// scratch
__device__ float  g_offmask[BB * 27 * HH * WW];                    // [b][ch][h][w]
__device__ __align__(16) __half g_x16[(size_t)BB * HH * WW * C1];  // [b][h][w][c] fp16
__device__ __align__(16) __half g_wk16[K2 * C2 * C1];              // [n][oc][c]
__device__ __align__(16) __half g_wom16[K2 * 32 * C1];             // [n][oc(27+pad)][c]

// ---------------------------------------------------------------------------
__device__ __forceinline__ uint32_t smem_u32(const void* p) {
    uint32_t a;
    asm("{ .reg .u64 t; cvta.to.shared.u64 t, %1; cvt.u32.u64 %0, t; }" : "=r"(a) : "l"(p));
    return a;
}
__device__ __forceinline__ void ldsm4(uint32_t addr, uint32_t* r) {
    asm volatile("ldmatrix.sync.aligned.m8n8.x4.shared.b16 {%0,%1,%2,%3}, [%4];"
                 : "=r"(r[0]), "=r"(r[1]), "=r"(r[2]), "=r"(r[3]) : "r"(addr));
}
__device__ __forceinline__ void mma16816(float* c, const uint32_t* a, uint32_t b0, uint32_t b1) {
    asm volatile("mma.sync.aligned.m16n8k16.row.col.f32.f16.f16.f32 "
                 "{%0,%1,%2,%3}, {%4,%5,%6,%7}, {%8,%9}, {%0,%1,%2,%3};"
                 : "+f"(c[0]), "+f"(c[1]), "+f"(c[2]), "+f"(c[3])
                 : "r"(a[0]), "r"(a[1]), "r"(a[2]), "r"(a[3]), "r"(b0), "r"(b1));
}

// ---------------------------------------------------------------------------
// prep 1: x[b][c][hw] -> g_x16[b][hw][c] (fp16 channels-last)
// ---------------------------------------------------------------------------
__global__ void __launch_bounds__(256) x16_kernel(const float* __restrict__ x) {
    __shared__ float t[128][33];
    const int b = blockIdx.y;
    const int pix0 = blockIdx.x * 32;
    const int px = threadIdx.x & 31, c0 = threadIdx.x >> 5;
#pragma unroll
    for (int k = 0; k < 16; k++) {
        int c = c0 + k * 8;
        t[c][px] = x[((size_t)(b * C1 + c) << 12) + pix0 + px];
    }
    __syncthreads();
    const int pix = threadIdx.x >> 3, cq = threadIdx.x & 7;
    __half* dst = g_x16 + ((((size_t)b << 12) + pix0 + pix) << 7);
#pragma unroll
    for (int k = 0; k < 4; k++) {
        int ce = (cq + k * 8) * 4;
        __half2 h0 = __floats2half2_rn(t[ce][pix], t[ce + 1][pix]);
        __half2 h1 = __floats2half2_rn(t[ce + 2][pix], t[ce + 3][pix]);
        uint2 v;
        v.x = *(uint32_t*)&h0;
        v.y = *(uint32_t*)&h1;
        *(uint2*)(dst + ce) = v;
    }
}

// ---------------------------------------------------------------------------
// prep 2: w_conv[oc][c][n] -> g_wk16[n][oc][c]
// ---------------------------------------------------------------------------
__global__ void wk16_kernel(const float* __restrict__ w_conv) {
    int i = blockIdx.x * 256 + threadIdx.x;
    if (i < K2 * C2 * C1) {
        int n = i / (C2 * C1);
        int r = i % (C2 * C1);
        int oc = r / C1, c = r % C1;
        g_wk16[i] = __float2half(w_conv[(oc * C1 + c) * K2 + n]);
    }
}

// ---------------------------------------------------------------------------
// prep 3: w_off[18][c][n], w_mask[9][c][n] -> g_wom16[n][oc32][c]
// ---------------------------------------------------------------------------
__global__ void wom16_kernel(const float* __restrict__ w_off, const float* __restrict__ w_mask) {
    int i = blockIdx.x * 256 + threadIdx.x;
    if (i < K2 * 32 * C1) {
        int n = i / (32 * C1);
        int r = i % (32 * C1);
        int oc = r / C1, c = r % C1;
        float v = 0.f;
        if (oc < 18)      v = w_off[(oc * C1 + c) * K2 + n];
        else if (oc < 27) v = w_mask[((oc - 18) * C1 + c) * K2 + n];
        g_wom16[i] = __float2half(v);
    }
}

// ---------------------------------------------------------------------------
// offset/mask conv as HMMA GEMM: 256 pixels x 32 outputs per CTA, K=9*128
// ---------------------------------------------------------------------------
#define OSA 136
#define OMG_B_OFF (256 * OSA * 2)                 // 69632
#define OMG_TOTAL (OMG_B_OFF + 32 * OSA * 2)      // 78336

__global__ void __launch_bounds__(256, 2) omg_kernel(
    const float* __restrict__ b_off, const float* __restrict__ b_mask)
{
    extern __shared__ char smem[];
    const uint32_t sb = smem_u32(smem);
    const int tid = threadIdx.x;
    const int lane = tid & 31;
    const int warp = tid >> 5;
    const int b = blockIdx.y;
    const int h0 = blockIdx.x * 4;

    float acc[2][4][4];
#pragma unroll
    for (int i = 0; i < 2; i++)
#pragma unroll
        for (int j = 0; j < 4; j++)
#pragma unroll
            for (int k = 0; k < 4; k++) acc[i][j][k] = 0.f;

    const int pixq = tid >> 3, chq = tid & 7;

    for (int n = 0; n < 9; n++) {
        if (n) __syncthreads();
        const int dy = n / 3 - 1, dx = n % 3 - 1;

        // A tile: shifted window copy from g_x16 (zero halo)
#pragma unroll
        for (int pass = 0; pass < 8; pass++) {
            const int pix = pass * 32 + pixq;
            const int h = h0 + (pix >> 6), w = pix & 63;
            const int sh = h + dy, sw = w + dx;
            const bool valid = ((unsigned)sh < HH) && ((unsigned)sw < WW);
            const uint4* src = (const uint4*)(g_x16 + (((size_t)(b << 12) + (sh << 6) + sw) << 7));
            uint32_t dstb = sb + (uint32_t)(pix * OSA) * 2;
#pragma unroll
            for (int j = 0; j < 2; j++) {
                uint4 v = make_uint4(0, 0, 0, 0);
                if (valid) v = src[chq + j * 8];
                asm volatile("st.shared.v4.b32 [%0], {%1,%2,%3,%4};"
                             :: "r"(dstb + (uint32_t)(chq + j * 8) * 16u),
                                "r"(v.x), "r"(v.y), "r"(v.z), "r"(v.w) : "memory");
            }
        }
        // B tile: 32 x 128 halves
        {
            const uint4* wsrc = (const uint4*)(g_wom16 + n * 32 * C1);
            for (int i = tid; i < 512; i += 256) {
                int row = i >> 4, seg = i & 15;
                uint4 v = wsrc[i];
                asm volatile("st.shared.v4.b32 [%0], {%1,%2,%3,%4};"
                             :: "r"(sb + OMG_B_OFF + (uint32_t)(row * OSA + seg * 8) * 2u),
                                "r"(v.x), "r"(v.y), "r"(v.z), "r"(v.w) : "memory");
            }
        }
        __syncthreads();

        const uint32_t rA = (uint32_t)(warp * 32 + (lane & 15));
        const uint32_t rB = (uint32_t)(lane & 15);
        const uint32_t cbase = (uint32_t)((lane >> 4) << 3);
#pragma unroll 2
        for (int kk = 0; kk < 8; kk++) {
            uint32_t col = kk * 16 + cbase;
            uint32_t a0[4], a1[4];
            ldsm4(sb + (rA * OSA + col) * 2, a0);
            ldsm4(sb + ((rA + 16) * OSA + col) * 2, a1);
            uint32_t bf[2][4];
#pragma unroll
            for (int t = 0; t < 2; t++)
                ldsm4(sb + OMG_B_OFF + ((rB + t * 16) * OSA + col) * 2, bf[t]);
#pragma unroll
            for (int t = 0; t < 2; t++) {
                mma16816(acc[0][2 * t],     a0, bf[t][0], bf[t][2]);
                mma16816(acc[0][2 * t + 1], a0, bf[t][1], bf[t][3]);
                mma16816(acc[1][2 * t],     a1, bf[t][0], bf[t][2]);
                mma16816(acc[1][2 * t + 1], a1, bf[t][1], bf[t][3]);
            }
        }
    }

    // epilogue: bias + sigmoid(mask), write g_offmask[b][ch][h][w]
#pragma unroll
    for (int mt = 0; mt < 2; mt++) {
#pragma unroll
        for (int nt = 0; nt < 4; nt++) {
            const float* c = acc[mt][nt];
            int m0 = warp * 32 + mt * 16 + (lane >> 2);
            int n0 = nt * 8 + (lane & 3) * 2;
#pragma unroll
            for (int q = 0; q < 4; q++) {
                int pix = m0 + (q >> 1) * 8;
                int oc = n0 + (q & 1);
                if (oc >= 27) continue;
                float v = c[q];
                if (oc < 18) v += b_off[oc];
                else         v = 1.f / (1.f + __expf(-(v + b_mask[oc - 18])));
                int h = h0 + (pix >> 6), w = pix & 63;
                g_offmask[(((b * 27 + oc) << 12)) + (h << 6) + w] = v;
            }
        }
    }
}

// ---------------------------------------------------------------------------
// main DCN: 128 pixels x 128 oc per CTA, HMMA, fp16 gather from g_x16
// ---------------------------------------------------------------------------
#define SA 136
#define SMEM_A_OFF  0
#define SMEM_B_OFF  (128 * SA * 2)              // 34816
#define SMEM_MI_OFF (2 * 128 * SA * 2)          // 69632
#define SMEM_MW_OFF (SMEM_MI_OFF + 2048)
#define SMEM_TOTAL  (SMEM_MW_OFF + 2048)        // 73728

__global__ void __launch_bounds__(256, 2) dcn_kernel(float* __restrict__ out)
{
    extern __shared__ char smem[];
    const uint32_t sb = smem_u32(smem);
    __half* Bs = (__half*)(smem + SMEM_B_OFF);
    int4*   metaI = (int4*)(smem + SMEM_MI_OFF);
    float4* metaW = (float4*)(smem + SMEM_MW_OFF);

    const int tid = threadIdx.x;
    const int lane = tid & 31;
    const int warp = tid >> 5;
    const int warp_m = warp & 3;
    const int warp_n = warp >> 2;
    const int b = blockIdx.x >> 5;
    const int h0 = (blockIdx.x & 31) << 1;

    float acc[2][8][4];
#pragma unroll
    for (int i = 0; i < 2; i++)
#pragma unroll
        for (int j = 0; j < 8; j++)
#pragma unroll
            for (int k = 0; k < 4; k++) acc[i][j][k] = 0.f;

    const int gpix_q = tid >> 3;
    const int chq = tid & 7;

    for (int n = 0; n < 9; n++) {
        if (n) __syncthreads();

        // ---- per-pixel bilinear metadata (element offsets into g_x16) ----
        if (tid < 128) {
            const int pix = tid;
            const int h = h0 + (pix >> 6), w = pix & 63;
            const float* om = g_offmask + ((size_t)b * 27 << 12) + (h << 6) + w;
            float offY = om[(size_t)(2 * n) << 12];
            float offX = om[(size_t)(2 * n + 1) << 12];
            float m    = om[(size_t)(18 + n) << 12];
            float py = offY + (float)(h - 1 + n / 3);
            float px = offX + (float)(w - 1 + n % 3);
            float fy = floorf(py), fx = floorf(px);
            int y0 = (int)fy, x0 = (int)fx;
            float wy1 = py - fy, wx1 = px - fx;
            float wy0 = 1.f - wy1, wx0 = 1.f - wx1;
            int y1 = y0 + 1, x1 = x0 + 1;
            bool vy0 = (y0 >= 0) & (y0 < HH), vy1 = (y1 >= 0) & (y1 < HH);
            bool vx0 = (x0 >= 0) & (x0 < WW), vx1 = (x1 >= 0) & (x1 < WW);
            int y0c = min(max(y0, 0), HH - 1), y1c = min(max(y1, 0), HH - 1);
            int x0c = min(max(x0, 0), WW - 1), x1c = min(max(x1, 0), WW - 1);
            int base = (b << 12);
            metaI[pix] = make_int4((base + (y0c << 6) + x0c) << 7,
                                   (base + (y0c << 6) + x1c) << 7,
                                   (base + (y1c << 6) + x0c) << 7,
                                   (base + (y1c << 6) + x1c) << 7);
            metaW[pix] = make_float4((vy0 && vx0) ? wy0 * wx0 * m : 0.f,
                                     (vy0 && vx1) ? wy0 * wx1 * m : 0.f,
                                     (vy1 && vx0) ? wy1 * wx0 * m : 0.f,
                                     (vy1 && vx1) ? wy1 * wx1 * m : 0.f);
        }
        __syncthreads();

        // ---- gather + bilinear -> fp16 A tile [pix][c] ----
#pragma unroll
        for (int pass = 0; pass < 4; pass++) {
            const int pix = pass * 32 + gpix_q;
            const int4   mi = metaI[pix];
            const float4 mw = metaW[pix];
            const uint4* p00 = (const uint4*)(g_x16 + mi.x);
            const uint4* p01 = (const uint4*)(g_x16 + mi.y);
            const uint4* p10 = (const uint4*)(g_x16 + mi.z);
            const uint4* p11 = (const uint4*)(g_x16 + mi.w);
            uint32_t rowbase = sb + SMEM_A_OFF + (uint32_t)(pix * SA) * 2;
#pragma unroll
            for (int j = 0; j < 2; j++) {
                const int seg = chq + j * 8;
                uint4 A4 = p00[seg], B4 = p01[seg], C4 = p10[seg], D4 = p11[seg];
                uint32_t o[4];
#pragma unroll
                for (int q = 0; q < 4; q++) {
                    float2 fa = __half22float2(((const __half2*)&A4)[q]);
                    float2 fb = __half22float2(((const __half2*)&B4)[q]);
                    float2 fc = __half22float2(((const __half2*)&C4)[q]);
                    float2 fd = __half22float2(((const __half2*)&D4)[q]);
                    float rx = mw.x * fa.x + mw.y * fb.x + mw.z * fc.x + mw.w * fd.x;
                    float ry = mw.x * fa.y + mw.y * fb.y + mw.z * fc.y + mw.w * fd.y;
                    __half2 hr = __floats2half2_rn(rx, ry);
                    o[q] = *(uint32_t*)&hr;
                }
                asm volatile("st.shared.v4.b32 [%0], {%1,%2,%3,%4};"
                             :: "r"(rowbase + (uint32_t)seg * 16u),
                                "r"(o[0]), "r"(o[1]), "r"(o[2]), "r"(o[3]) : "memory");
            }
        }

        // ---- B tile copy [oc][c] ----
        {
            const float4* src = (const float4*)(g_wk16 + n * (C2 * C1));
            for (int i = tid; i < 2048; i += 256) {
                int row = i >> 4, seg = i & 15;
                *(float4*)(Bs + row * SA + seg * 8) = src[i];
            }
        }
        __syncthreads();

        // ---- HMMA over 8 k-steps ----
        const uint32_t rA = (uint32_t)(warp_m * 32 + (lane & 15));
        const uint32_t rB = (uint32_t)(warp_n * 64 + (lane & 15));
        const uint32_t cbase = (uint32_t)((lane >> 4) << 3);
#pragma unroll 2
        for (int kk = 0; kk < 8; kk++) {
            uint32_t col = kk * 16 + cbase;
            uint32_t a0[4], a1[4];
            ldsm4(sb + SMEM_A_OFF + (rA * SA + col) * 2, a0);
            ldsm4(sb + SMEM_A_OFF + ((rA + 16) * SA + col) * 2, a1);
            uint32_t bf[4][4];
#pragma unroll
            for (int t = 0; t < 4; t++)
                ldsm4(sb + SMEM_B_OFF + ((rB + t * 16) * SA + col) * 2, bf[t]);
#pragma unroll
            for (int t = 0; t < 4; t++) {
                mma16816(acc[0][2 * t],     a0, bf[t][0], bf[t][2]);
                mma16816(acc[0][2 * t + 1], a0, bf[t][1], bf[t][3]);
                mma16816(acc[1][2 * t],     a1, bf[t][0], bf[t][2]);
                mma16816(acc[1][2 * t + 1], a1, bf[t][1], bf[t][3]);
            }
        }
    }

    // ---- epilogue ----
    const size_t obase = ((size_t)b * C2 << 12) + (size_t)h0 * 64;
#pragma unroll
    for (int mt = 0; mt < 2; mt++) {
#pragma unroll
        for (int nt = 0; nt < 8; nt++) {
            const float* c = acc[mt][nt];
            int m0 = warp_m * 32 + mt * 16 + (lane >> 2);
            int n0 = warp_n * 64 + nt * 8 + (lane & 3) * 2;
            float* o0 = out + obase + ((size_t)n0 << 12);
            float* o1 = o0 + 4096;
            o0[m0]     = c[0];
            o1[m0]     = c[1];
            o0[m0 + 8] = c[2];
            o1[m0 + 8] = c[3];
        }
    }
}

// ---------------------------------------------------------------------------
extern "C" void kernel_launch(void* const* d_in, const int* in_sizes, int n_in,
                              void* d_out, int out_size) {
    const float* x      = (const float*)d_in[0];
    const float* w_conv = (const float*)d_in[1];
    const float* w_off  = (const float*)d_in[2];
    const float* b_off  = (const float*)d_in[3];
    const float* w_mask = (const float*)d_in[4];
    const float* b_mask = (const float*)d_in[5];
    float* out = (float*)d_out;

    cudaFuncSetAttribute(dcn_kernel, cudaFuncAttributeMaxDynamicSharedMemorySize, SMEM_TOTAL);
    cudaFuncSetAttribute(omg_kernel, cudaFuncAttributeMaxDynamicSharedMemorySize, OMG_TOTAL);

    wk16_kernel<<<(K2 * C2 * C1 + 255) / 256, 256>>>(w_conv);
    wom16_kernel<<<(K2 * 32 * C1 + 255) / 256, 256>>>(w_off, w_mask);

    dim3 gT(HH * WW / 32, BB);
    x16_kernel<<<gT, 256>>>(x);

    dim3 gO(HH / 4, BB);
    omg_kernel<<<gO, 256, OMG_TOTAL>>>(b_off, b_mask);

    dcn_kernel<<<BB * HH / 2, 256, SMEM_TOTAL>>>(out);
}